// round 14
// baseline (speedup 1.0000x reference)
#include <cuda_runtime.h>
#include <cuda_fp16.h>

typedef unsigned long long ull;

#define DQ    512
#define H1Q   16
#define CQ    40
#define N_MAX 100000
#define NNZ_MAX 3200000

#define TK     4                  // k-cols per tile (one float4 per row)
#define NT     (DQ / TK)          // 128 tiles
#define PADW   4                  // floats per staged row (16B, no pad needed)

#define CAP     128               // ELL slots per row (max expected deg ~59)
#define OVF_MAX 8192

// ------------------------------ scratch -------------------------------------
__device__ uint2 g_X1h[N_MAX * 4];           // H @ W1, fp16
__device__ uint2 g_Zh [N_MAX * 4];           // relu(A @ X1 + b1), fp16
__device__ int   g_cnt[N_MAX + 1];           // per-row degree; [N_MAX] = ovf count
__device__ int2  g_ell[(size_t)N_MAX * CAP]; // ELL: {col, val_bits}
__device__ int4  g_ovf[OVF_MAX];             // overflow: {row, col, val_bits, 0}

// ------------------------------ helpers -------------------------------------
__device__ __forceinline__ ull fma2(ull a, ull b, ull c) {
    ull d;
    asm("fma.rn.f32x2 %0, %1, %2, %3;" : "=l"(d) : "l"(a), "l"(b), "l"(c));
    return d;
}
__device__ __forceinline__ ull pack2(float x) {
    ull d;
    asm("mov.b64 %0, {%1, %1};" : "=l"(d) : "f"(x));
    return d;
}
__device__ __forceinline__ float2 unpack2(ull v) {
    float a, b;
    asm("mov.b64 {%0, %1}, %2;" : "=f"(a), "=f"(b) : "l"(v));
    return make_float2(a, b);
}
__device__ __forceinline__ unsigned h2pack(ull v) {
    float2 f = unpack2(v);
    __half2 h = __float22half2_rn(f);
    return *reinterpret_cast<unsigned*>(&h);
}
__device__ __forceinline__ float2 h2unpack(unsigned u) {
    __half2 h = *reinterpret_cast<__half2*>(&u);
    return __half22float2(h);
}
__device__ __forceinline__ unsigned smem_u32(const void* p) {
    return (unsigned)__cvta_generic_to_shared(p);
}
__device__ __forceinline__ void cp_async16(unsigned s, const void* g) {
    asm volatile("cp.async.cg.shared.global [%0], [%1], 16;" :: "r"(s), "l"(g));
}
__device__ __forceinline__ void cp_commit() {
    asm volatile("cp.async.commit_group;");
}
template <int N>
__device__ __forceinline__ void cp_wait() {
    asm volatile("cp.async.wait_group %0;" :: "n"(N));
}

__device__ __forceinline__ void ell_store(int r, int c, int vbits) {
    int s = atomicAdd(&g_cnt[r], 1);
    if (s < CAP) {
        g_ell[(size_t)r * CAP + s] = make_int2(c, vbits);
    } else {
        int o = atomicAdd(&g_cnt[N_MAX], 1);
        if (o < OVF_MAX) g_ovf[o] = make_int4(r, c, vbits, 0);
    }
}

// ------------------------------ fused GEMM + ELL scatter ---------------------
// gemm blocks: 8 per-warp pipelines; warp owns 64 rows (2 rows/thread), TK=4,
// double-buffered cp.async (16KB staging + 32KB W = 48KB smem, 3 CTA/SM).
// scatter blocks: 8 edges/thread, builds ELL directly.
__global__ void __launch_bounds__(256, 3) gemm_scatter_kernel(
        const float* __restrict__ Hm, const float* __restrict__ W1,
        const int* __restrict__ rows, const int* __restrict__ cols,
        const float* __restrict__ vals, int n, int nnz, int gemm_blocks) {
    __shared__ ull   sW2[DQ * 8];               // 32KB  [k][pair0..7]
    __shared__ float sH[8][2][64 * PADW];       // 8 x 2KB = 16KB

    if ((int)blockIdx.x < gemm_blocks) {
        int tid  = threadIdx.x;
        int warp = tid >> 5;
        int lane = tid & 31;
        int rbase = (blockIdx.x * 8 + warp) * 64;
        int ra = rbase + lane;
        int rb = ra + 32;

        // W via cp.async (group 0)
#pragma unroll
        for (int j = 0; j < 8; j++) {
            int i = tid + 256 * j;
            cp_async16(smem_u32(reinterpret_cast<float4*>(sW2) + i),
                       reinterpret_cast<const float4*>(W1) + i);
        }
        // stage tile 0 (group 0): 64 rows x 16B = 2 chunks/thread
#pragma unroll
        for (int j = 0; j < 2; j++) {
            int r = lane + 32 * j;
            int grow = rbase + r;
            if (grow < n)
                cp_async16(smem_u32(&sH[warp][0][r * PADW]),
                           Hm + (size_t)grow * DQ);
        }
        cp_commit();

        ull accA[8], accB[8];
        ull z = pack2(0.f);
#pragma unroll
        for (int p = 0; p < 8; p++) { accA[p] = z; accB[p] = z; }

        const ulonglong2* wv = reinterpret_cast<const ulonglong2*>(sW2);

        for (int t = 0; t < NT; t++) {
            int buf = t & 1;
            if (t + 1 < NT) {
#pragma unroll
                for (int j = 0; j < 2; j++) {
                    int r = lane + 32 * j;
                    int grow = rbase + r;
                    if (grow < n)
                        cp_async16(smem_u32(&sH[warp][buf ^ 1][r * PADW]),
                                   Hm + (size_t)grow * DQ + (t + 1) * TK);
                }
                cp_commit();
                cp_wait<1>();
            } else {
                cp_wait<0>();
            }
            __syncwarp();
            if (t == 0) __syncthreads();         // W visible to all warps

            float4 hA = *reinterpret_cast<const float4*>(&sH[warp][buf][lane * PADW]);
            float4 hB = *reinterpret_cast<const float4*>(&sH[warp][buf][(lane + 32) * PADW]);
            float a4[4] = {hA.x, hA.y, hA.z, hA.w};
            float b4[4] = {hB.x, hB.y, hB.z, hB.w};
#pragma unroll
            for (int j = 0; j < 4; j++) {
                int k = t * TK + j;
                ull pa = pack2(a4[j]);
                ull pb = pack2(b4[j]);
#pragma unroll
                for (int p = 0; p < 4; p++) {
                    ulonglong2 w = wv[k * 4 + p];
                    accA[2 * p + 0] = fma2(pa, w.x, accA[2 * p + 0]);
                    accA[2 * p + 1] = fma2(pa, w.y, accA[2 * p + 1]);
                    accB[2 * p + 0] = fma2(pb, w.x, accB[2 * p + 0]);
                    accB[2 * p + 1] = fma2(pb, w.y, accB[2 * p + 1]);
                }
            }
            __syncwarp();
        }

        if (ra < n) {
            uint2* o = &g_X1h[(size_t)ra * 4];
#pragma unroll
            for (int q = 0; q < 4; q++)
                o[q] = make_uint2(h2pack(accA[2 * q]), h2pack(accA[2 * q + 1]));
        }
        if (rb < n) {
            uint2* o = &g_X1h[(size_t)rb * 4];
#pragma unroll
            for (int q = 0; q < 4; q++)
                o[q] = make_uint2(h2pack(accB[2 * q]), h2pack(accB[2 * q + 1]));
        }
    } else {
        int idx = (blockIdx.x - gemm_blocks) * 256 + threadIdx.x;
        int nv = nnz >> 3;                       // 8 edges per thread
        if (idx < nv) {
            const int4* r4p = reinterpret_cast<const int4*>(rows);
            const int4* c4p = reinterpret_cast<const int4*>(cols);
            const float4* v4p = reinterpret_cast<const float4*>(vals);
            int4   r0 = r4p[2 * idx],     r1 = r4p[2 * idx + 1];
            int4   c0 = c4p[2 * idx],     c1 = c4p[2 * idx + 1];
            float4 v0 = v4p[2 * idx],     v1 = v4p[2 * idx + 1];
            ell_store(r0.x, c0.x, __float_as_int(v0.x));
            ell_store(r0.y, c0.y, __float_as_int(v0.y));
            ell_store(r0.z, c0.z, __float_as_int(v0.z));
            ell_store(r0.w, c0.w, __float_as_int(v0.w));
            ell_store(r1.x, c1.x, __float_as_int(v1.x));
            ell_store(r1.y, c1.y, __float_as_int(v1.y));
            ell_store(r1.z, c1.z, __float_as_int(v1.z));
            ell_store(r1.w, c1.w, __float_as_int(v1.w));
        } else if (idx == nv) {
            for (int e = nv * 8; e < nnz; e++)
                ell_store(rows[e], cols[e], __float_as_int(vals[e]));
        }
    }
}

// ------------------------------ SpMM gather core (MLP=16) --------------------
__device__ __forceinline__ float4 gather_row(const uint2* __restrict__ X,
                                             const int2* __restrict__ ed,
                                             int deg, int sub) {
    float4 acc = make_float4(0, 0, 0, 0);
    int i = 0;
    for (; i + 16 <= deg; i += 16) {
        int2  e[16];
        uint2 x[16];
#pragma unroll
        for (int j = 0; j < 16; j++) e[j] = ed[i + j];
#pragma unroll
        for (int j = 0; j < 16; j++) x[j] = X[(size_t)e[j].x * 4 + sub];
#pragma unroll
        for (int j = 0; j < 16; j++) {
            float v = __int_as_float(e[j].y);
            float2 lo = h2unpack(x[j].x), hi = h2unpack(x[j].y);
            acc.x = fmaf(v, lo.x, acc.x); acc.y = fmaf(v, lo.y, acc.y);
            acc.z = fmaf(v, hi.x, acc.z); acc.w = fmaf(v, hi.y, acc.w);
        }
    }
    for (; i + 4 <= deg; i += 4) {
        int2  e[4];
        uint2 x[4];
#pragma unroll
        for (int j = 0; j < 4; j++) e[j] = ed[i + j];
#pragma unroll
        for (int j = 0; j < 4; j++) x[j] = X[(size_t)e[j].x * 4 + sub];
#pragma unroll
        for (int j = 0; j < 4; j++) {
            float v = __int_as_float(e[j].y);
            float2 lo = h2unpack(x[j].x), hi = h2unpack(x[j].y);
            acc.x = fmaf(v, lo.x, acc.x); acc.y = fmaf(v, lo.y, acc.y);
            acc.z = fmaf(v, hi.x, acc.z); acc.w = fmaf(v, hi.y, acc.w);
        }
    }
    for (; i < deg; i++) {
        int2 e = ed[i];
        float v = __int_as_float(e.y);
        uint2 xh = X[(size_t)e.x * 4 + sub];
        float2 lo = h2unpack(xh.x), hi = h2unpack(xh.y);
        acc.x = fmaf(v, lo.x, acc.x); acc.y = fmaf(v, lo.y, acc.y);
        acc.z = fmaf(v, hi.x, acc.z); acc.w = fmaf(v, hi.y, acc.w);
    }
    return acc;
}

// overflow edges (normally zero) — correctness safety net
__device__ __forceinline__ float4 gather_ovf(const uint2* __restrict__ X,
                                             int row, int sub, float4 acc) {
    int novf = g_cnt[N_MAX];
    for (int i = 0; i < novf && i < OVF_MAX; i++) {
        int4 e = g_ovf[i];
        if (e.x == row) {
            float v = __int_as_float(e.z);
            uint2 xh = X[(size_t)e.y * 4 + sub];
            float2 lo = h2unpack(xh.x), hi = h2unpack(xh.y);
            acc.x = fmaf(v, lo.x, acc.x); acc.y = fmaf(v, lo.y, acc.y);
            acc.z = fmaf(v, hi.x, acc.z); acc.w = fmaf(v, hi.y, acc.w);
        }
    }
    return acc;
}

// ------------------------------ SpMM 1 ---------------------------------------
__global__ void spmm1_kernel(const float* __restrict__ b1, int n) {
    int wg   = (blockIdx.x * blockDim.x + threadIdx.x) >> 5;
    int lane = threadIdx.x & 31;
    int rloc = lane >> 2, sub = lane & 3;
    int row  = wg * 8 + rloc;
    if (row >= n) return;

    int deg = min(g_cnt[row], CAP);
    const float4 b = reinterpret_cast<const float4*>(b1)[sub];

    float4 acc = gather_row(g_X1h, g_ell + (size_t)row * CAP, deg, sub);
    acc = gather_ovf(g_X1h, row, sub, acc);

    float2 z0 = make_float2(fmaxf(acc.x + b.x, 0.f), fmaxf(acc.y + b.y, 0.f));
    float2 z1 = make_float2(fmaxf(acc.z + b.z, 0.f), fmaxf(acc.w + b.w, 0.f));
    __half2 h0 = __float22half2_rn(z0);
    __half2 h1 = __float22half2_rn(z1);
    g_Zh[(size_t)row * 4 + sub] =
        make_uint2(*reinterpret_cast<unsigned*>(&h0), *reinterpret_cast<unsigned*>(&h1));
}

// ------------------------------ SpMM 2 + epilogue ----------------------------
__global__ void __launch_bounds__(256) spmm2_epi_kernel(
        const float* __restrict__ W2, const float* __restrict__ b2,
        float* __restrict__ out, int n) {
    __shared__ float sY[64 * 17];
    __shared__ float sW[H1Q * CQ];
    __shared__ float sB[CQ];

    for (int i = threadIdx.x; i < H1Q * CQ; i += blockDim.x) sW[i] = W2[i];
    if (threadIdx.x < CQ) sB[threadIdx.x] = b2[threadIdx.x];

    int warp  = threadIdx.x >> 5;
    int lane  = threadIdx.x & 31;
    int rloc  = warp * 8 + (lane >> 2);
    int sub   = lane & 3;
    int rbase = blockIdx.x * 64;
    int row   = rbase + rloc;

    float4 acc = make_float4(0, 0, 0, 0);
    if (row < n) {
        int deg = min(g_cnt[row], CAP);
        acc = gather_row(g_Zh, g_ell + (size_t)row * CAP, deg, sub);
        acc = gather_ovf(g_Zh, row, sub, acc);
    }
    float* sy = &sY[rloc * 17 + sub * 4];
    sy[0] = acc.x; sy[1] = acc.y; sy[2] = acc.z; sy[3] = acc.w;
    __syncthreads();

    // epilogue: thread t -> row t>>2, columns [10*(t&3), 10*(t&3)+10)
    int t    = threadIdx.x;
    int erow = t >> 2;
    int part = t & 3;
    if (rbase + erow < n) {
        float y[16];
#pragma unroll
        for (int k = 0; k < 16; k++) y[k] = sY[erow * 17 + k];

        float o[10];
#pragma unroll
        for (int c = 0; c < 10; c++) o[c] = sB[part * 10 + c];
#pragma unroll
        for (int k = 0; k < H1Q; k++) {
            float h = y[k];
#pragma unroll
            for (int c = 0; c < 10; c++)
                o[c] = fmaf(h, sW[k * CQ + part * 10 + c], o[c]);
        }
        float m = 0.f;                      // relu floor
#pragma unroll
        for (int c = 0; c < 10; c++) {
            o[c] = fmaxf(o[c], 0.f);
            m = fmaxf(m, o[c]);
        }
        m = fmaxf(m, __shfl_xor_sync(0xffffffffu, m, 1));
        m = fmaxf(m, __shfl_xor_sync(0xffffffffu, m, 2));
        float s = 0.f;
#pragma unroll
        for (int c = 0; c < 10; c++) s += __expf(o[c] - m);
        s += __shfl_xor_sync(0xffffffffu, s, 1);
        s += __shfl_xor_sync(0xffffffffu, s, 2);
        float l = __logf(s) + m;

        float2* op = reinterpret_cast<float2*>(
            out + (size_t)(rbase + erow) * CQ + part * 10);
#pragma unroll
        for (int q = 0; q < 5; q++)
            op[q] = make_float2(o[2 * q] - l, o[2 * q + 1] - l);
    }
}

// ---------------------------------------------------------------------------
// Inputs (metadata order): H, A_vals, W1, b1, W2, b2, A_rows, A_cols
// ---------------------------------------------------------------------------
extern "C" void kernel_launch(void* const* d_in, const int* in_sizes, int n_in,
                              void* d_out, int out_size) {
    const float* Hm     = (const float*)d_in[0];
    const float* A_vals = (const float*)d_in[1];
    const float* W1     = (const float*)d_in[2];
    const float* b1     = (const float*)d_in[3];
    const float* W2     = (const float*)d_in[4];
    const float* b2     = (const float*)d_in[5];
    const int*   A_rows = (const int*)d_in[6];
    const int*   A_cols = (const int*)d_in[7];

    int n   = in_sizes[0] / DQ;
    int nnz = in_sizes[1];
    float* out = (float*)d_out;

    void* cnt_ptr = nullptr;
    cudaGetSymbolAddress(&cnt_ptr, g_cnt);
    cudaMemsetAsync(cnt_ptr, 0, (size_t)(N_MAX + 1) * sizeof(int), 0);

    int gemm_blocks    = (n + 511) / 512;
    int scatter_blocks = (nnz / 8 + 256) / 256;
    gemm_scatter_kernel<<<gemm_blocks + scatter_blocks, 256>>>(
        Hm, W1, A_rows, A_cols, A_vals, n, nnz, gemm_blocks);

    spmm1_kernel<<<(n + 63) / 64, 256>>>(b1, n);
    spmm2_epi_kernel<<<(n + 63) / 64, 256>>>(W2, b2, out, n);
}

// round 15
// speedup vs baseline: 1.2355x; 1.2355x over previous
#include <cuda_runtime.h>
#include <cuda_fp16.h>

typedef unsigned long long ull;

#define DQ    512
#define H1Q   16
#define CQ    40
#define N_MAX 100000
#define NNZ_MAX 3200000

#define TK     8                  // k-cols per tile
#define NT     (DQ / TK)          // 64 tiles
#define PADW   12                 // floats per staged row (8 + 4 pad)

#define CAP     128               // ELL slots per row (max expected deg ~59)
#define OVF_MAX 8192

// ------------------------------ scratch -------------------------------------
__device__ uint2 g_X1h[N_MAX * 4];           // H @ W1, fp16
__device__ uint2 g_Zh [N_MAX * 4];           // relu(A @ X1 + b1), fp16
__device__ int   g_cnt[N_MAX + 1];           // per-row degree; [N_MAX] = ovf count
__device__ int2  g_ell[(size_t)N_MAX * CAP]; // ELL: {col, val_bits}
__device__ int4  g_ovf[OVF_MAX];             // overflow: {row, col, val_bits, 0}

// ------------------------------ helpers -------------------------------------
__device__ __forceinline__ ull fma2(ull a, ull b, ull c) {
    ull d;
    asm("fma.rn.f32x2 %0, %1, %2, %3;" : "=l"(d) : "l"(a), "l"(b), "l"(c));
    return d;
}
__device__ __forceinline__ ull pack2(float x) {
    ull d;
    asm("mov.b64 %0, {%1, %1};" : "=l"(d) : "f"(x));
    return d;
}
__device__ __forceinline__ float2 unpack2(ull v) {
    float a, b;
    asm("mov.b64 {%0, %1}, %2;" : "=f"(a), "=f"(b) : "l"(v));
    return make_float2(a, b);
}
__device__ __forceinline__ unsigned h2pack(ull v) {
    float2 f = unpack2(v);
    __half2 h = __float22half2_rn(f);
    return *reinterpret_cast<unsigned*>(&h);
}
__device__ __forceinline__ float2 h2unpack(unsigned u) {
    __half2 h = *reinterpret_cast<__half2*>(&u);
    return __half22float2(h);
}
__device__ __forceinline__ unsigned smem_u32(const void* p) {
    return (unsigned)__cvta_generic_to_shared(p);
}
__device__ __forceinline__ void cp_async16(unsigned s, const void* g) {
    asm volatile("cp.async.cg.shared.global [%0], [%1], 16;" :: "r"(s), "l"(g));
}
__device__ __forceinline__ void cp_commit() {
    asm volatile("cp.async.commit_group;");
}
template <int N>
__device__ __forceinline__ void cp_wait() {
    asm volatile("cp.async.wait_group %0;" :: "n"(N));
}

__device__ __forceinline__ void ell_store(int r, int c, int vbits) {
    int s = atomicAdd(&g_cnt[r], 1);
    if (s < CAP) {
        g_ell[(size_t)r * CAP + s] = make_int2(c, vbits);
    } else {
        int o = atomicAdd(&g_cnt[N_MAX], 1);
        if (o < OVF_MAX) g_ovf[o] = make_int4(r, c, vbits, 0);
    }
}

// ------------------------------ fused GEMM + ELL scatter ---------------------
// gemm blocks (R13 config): 8 per-warp pipelines; warp owns 64 rows (2 rows/
// thread), TK=8, double-buffered cp.async, W1 broadcast from smem.
// scatter blocks: 8 edges/thread, builds ELL directly.
__global__ void __launch_bounds__(256) gemm_scatter_kernel(
        const float* __restrict__ Hm, const float* __restrict__ W1,
        const int* __restrict__ rows, const int* __restrict__ cols,
        const float* __restrict__ vals, int n, int nnz, int gemm_blocks) {
    __shared__ ull   sW2[DQ * 8];               // 32KB  [k][pair0..7]
    __shared__ float sH[8][2][64 * PADW];       // 8 x 6KB

    if ((int)blockIdx.x < gemm_blocks) {
        int tid  = threadIdx.x;
        int warp = tid >> 5;
        int lane = tid & 31;
        int rbase = (blockIdx.x * 8 + warp) * 64;
        int ra = rbase + lane;
        int rb = ra + 32;

        // W via cp.async (group 0)
#pragma unroll
        for (int j = 0; j < 8; j++) {
            int i = tid + 256 * j;
            cp_async16(smem_u32(reinterpret_cast<float4*>(sW2) + i),
                       reinterpret_cast<const float4*>(W1) + i);
        }
        // stage tile 0 (group 0)
#pragma unroll
        for (int j = 0; j < 4; j++) {
            int i = lane + 32 * j;
            int r = i >> 1, q = i & 1;
            int grow = rbase + r;
            if (grow < n)
                cp_async16(smem_u32(&sH[warp][0][r * PADW + q * 4]),
                           Hm + (size_t)grow * DQ + q * 4);
        }
        cp_commit();

        ull accA[8], accB[8];
        ull z = pack2(0.f);
#pragma unroll
        for (int p = 0; p < 8; p++) { accA[p] = z; accB[p] = z; }

        const ulonglong2* wv = reinterpret_cast<const ulonglong2*>(sW2);

        for (int t = 0; t < NT; t++) {
            int buf = t & 1;
            if (t + 1 < NT) {
#pragma unroll
                for (int j = 0; j < 4; j++) {
                    int i = lane + 32 * j;
                    int r = i >> 1, q = i & 1;
                    int grow = rbase + r;
                    if (grow < n)
                        cp_async16(smem_u32(&sH[warp][buf ^ 1][r * PADW + q * 4]),
                                   Hm + (size_t)grow * DQ + (t + 1) * TK + q * 4);
                }
                cp_commit();
                cp_wait<1>();
            } else {
                cp_wait<0>();
            }
            __syncwarp();
            if (t == 0) __syncthreads();         // W visible to all warps

            const float* hrA = &sH[warp][buf][lane * PADW];
            const float* hrB = &sH[warp][buf][(lane + 32) * PADW];
#pragma unroll
            for (int q = 0; q < 2; q++) {
                float4 hA = *reinterpret_cast<const float4*>(hrA + q * 4);
                float4 hB = *reinterpret_cast<const float4*>(hrB + q * 4);
                float a4[4] = {hA.x, hA.y, hA.z, hA.w};
                float b4[4] = {hB.x, hB.y, hB.z, hB.w};
#pragma unroll
                for (int j = 0; j < 4; j++) {
                    int k = t * TK + q * 4 + j;
                    ull pa = pack2(a4[j]);
                    ull pb = pack2(b4[j]);
#pragma unroll
                    for (int p = 0; p < 4; p++) {
                        ulonglong2 w = wv[k * 4 + p];
                        accA[2 * p + 0] = fma2(pa, w.x, accA[2 * p + 0]);
                        accA[2 * p + 1] = fma2(pa, w.y, accA[2 * p + 1]);
                        accB[2 * p + 0] = fma2(pb, w.x, accB[2 * p + 0]);
                        accB[2 * p + 1] = fma2(pb, w.y, accB[2 * p + 1]);
                    }
                }
            }
            __syncwarp();
        }

        if (ra < n) {
            uint2* o = &g_X1h[(size_t)ra * 4];
#pragma unroll
            for (int q = 0; q < 4; q++)
                o[q] = make_uint2(h2pack(accA[2 * q]), h2pack(accA[2 * q + 1]));
        }
        if (rb < n) {
            uint2* o = &g_X1h[(size_t)rb * 4];
#pragma unroll
            for (int q = 0; q < 4; q++)
                o[q] = make_uint2(h2pack(accB[2 * q]), h2pack(accB[2 * q + 1]));
        }
    } else {
        int idx = (blockIdx.x - gemm_blocks) * 256 + threadIdx.x;
        int nv = nnz >> 3;                       // 8 edges per thread
        if (idx < nv) {
            const int4* r4p = reinterpret_cast<const int4*>(rows);
            const int4* c4p = reinterpret_cast<const int4*>(cols);
            const float4* v4p = reinterpret_cast<const float4*>(vals);
            int4   r0 = r4p[2 * idx],     r1 = r4p[2 * idx + 1];
            int4   c0 = c4p[2 * idx],     c1 = c4p[2 * idx + 1];
            float4 v0 = v4p[2 * idx],     v1 = v4p[2 * idx + 1];
            ell_store(r0.x, c0.x, __float_as_int(v0.x));
            ell_store(r0.y, c0.y, __float_as_int(v0.y));
            ell_store(r0.z, c0.z, __float_as_int(v0.z));
            ell_store(r0.w, c0.w, __float_as_int(v0.w));
            ell_store(r1.x, c1.x, __float_as_int(v1.x));
            ell_store(r1.y, c1.y, __float_as_int(v1.y));
            ell_store(r1.z, c1.z, __float_as_int(v1.z));
            ell_store(r1.w, c1.w, __float_as_int(v1.w));
        } else if (idx == nv) {
            for (int e = nv * 8; e < nnz; e++)
                ell_store(rows[e], cols[e], __float_as_int(vals[e]));
        }
    }
}

// ------------------------------ SpMM gather core (MLP=16) --------------------
__device__ __forceinline__ float4 gather_row(const uint2* __restrict__ X,
                                             const int2* __restrict__ ed,
                                             int deg, int sub) {
    float4 acc = make_float4(0, 0, 0, 0);
    int i = 0;
    for (; i + 16 <= deg; i += 16) {
        int2  e[16];
        uint2 x[16];
#pragma unroll
        for (int j = 0; j < 16; j++) e[j] = ed[i + j];
#pragma unroll
        for (int j = 0; j < 16; j++) x[j] = X[(size_t)e[j].x * 4 + sub];
#pragma unroll
        for (int j = 0; j < 16; j++) {
            float v = __int_as_float(e[j].y);
            float2 lo = h2unpack(x[j].x), hi = h2unpack(x[j].y);
            acc.x = fmaf(v, lo.x, acc.x); acc.y = fmaf(v, lo.y, acc.y);
            acc.z = fmaf(v, hi.x, acc.z); acc.w = fmaf(v, hi.y, acc.w);
        }
    }
    for (; i + 4 <= deg; i += 4) {
        int2  e[4];
        uint2 x[4];
#pragma unroll
        for (int j = 0; j < 4; j++) e[j] = ed[i + j];
#pragma unroll
        for (int j = 0; j < 4; j++) x[j] = X[(size_t)e[j].x * 4 + sub];
#pragma unroll
        for (int j = 0; j < 4; j++) {
            float v = __int_as_float(e[j].y);
            float2 lo = h2unpack(x[j].x), hi = h2unpack(x[j].y);
            acc.x = fmaf(v, lo.x, acc.x); acc.y = fmaf(v, lo.y, acc.y);
            acc.z = fmaf(v, hi.x, acc.z); acc.w = fmaf(v, hi.y, acc.w);
        }
    }
    for (; i < deg; i++) {
        int2 e = ed[i];
        float v = __int_as_float(e.y);
        uint2 xh = X[(size_t)e.x * 4 + sub];
        float2 lo = h2unpack(xh.x), hi = h2unpack(xh.y);
        acc.x = fmaf(v, lo.x, acc.x); acc.y = fmaf(v, lo.y, acc.y);
        acc.z = fmaf(v, hi.x, acc.z); acc.w = fmaf(v, hi.y, acc.w);
    }
    return acc;
}

// overflow edges (normally zero) — correctness safety net
__device__ __forceinline__ float4 gather_ovf(const uint2* __restrict__ X,
                                             int row, int sub, float4 acc) {
    int novf = g_cnt[N_MAX];
    for (int i = 0; i < novf && i < OVF_MAX; i++) {
        int4 e = g_ovf[i];
        if (e.x == row) {
            float v = __int_as_float(e.z);
            uint2 xh = X[(size_t)e.y * 4 + sub];
            float2 lo = h2unpack(xh.x), hi = h2unpack(xh.y);
            acc.x = fmaf(v, lo.x, acc.x); acc.y = fmaf(v, lo.y, acc.y);
            acc.z = fmaf(v, hi.x, acc.z); acc.w = fmaf(v, hi.y, acc.w);
        }
    }
    return acc;
}

// ------------------------------ SpMM 1 ---------------------------------------
__global__ void spmm1_kernel(const float* __restrict__ b1, int n) {
    int wg   = (blockIdx.x * blockDim.x + threadIdx.x) >> 5;
    int lane = threadIdx.x & 31;
    int rloc = lane >> 2, sub = lane & 3;
    int row  = wg * 8 + rloc;
    if (row >= n) return;

    int deg = min(g_cnt[row], CAP);
    const float4 b = reinterpret_cast<const float4*>(b1)[sub];

    float4 acc = gather_row(g_X1h, g_ell + (size_t)row * CAP, deg, sub);
    acc = gather_ovf(g_X1h, row, sub, acc);

    float2 z0 = make_float2(fmaxf(acc.x + b.x, 0.f), fmaxf(acc.y + b.y, 0.f));
    float2 z1 = make_float2(fmaxf(acc.z + b.z, 0.f), fmaxf(acc.w + b.w, 0.f));
    __half2 h0 = __float22half2_rn(z0);
    __half2 h1 = __float22half2_rn(z1);
    g_Zh[(size_t)row * 4 + sub] =
        make_uint2(*reinterpret_cast<unsigned*>(&h0), *reinterpret_cast<unsigned*>(&h1));
}

// ------------------------------ SpMM 2 + epilogue ----------------------------
__global__ void __launch_bounds__(256) spmm2_epi_kernel(
        const float* __restrict__ W2, const float* __restrict__ b2,
        float* __restrict__ out, int n) {
    __shared__ float sY[64 * 17];
    __shared__ float sW[H1Q * CQ];
    __shared__ float sB[CQ];

    for (int i = threadIdx.x; i < H1Q * CQ; i += blockDim.x) sW[i] = W2[i];
    if (threadIdx.x < CQ) sB[threadIdx.x] = b2[threadIdx.x];

    int warp  = threadIdx.x >> 5;
    int lane  = threadIdx.x & 31;
    int rloc  = warp * 8 + (lane >> 2);
    int sub   = lane & 3;
    int rbase = blockIdx.x * 64;
    int row   = rbase + rloc;

    float4 acc = make_float4(0, 0, 0, 0);
    if (row < n) {
        int deg = min(g_cnt[row], CAP);
        acc = gather_row(g_Zh, g_ell + (size_t)row * CAP, deg, sub);
        acc = gather_ovf(g_Zh, row, sub, acc);
    }
    float* sy = &sY[rloc * 17 + sub * 4];
    sy[0] = acc.x; sy[1] = acc.y; sy[2] = acc.z; sy[3] = acc.w;
    __syncthreads();

    // epilogue: thread t -> row t>>2, columns [10*(t&3), 10*(t&3)+10)
    int t    = threadIdx.x;
    int erow = t >> 2;
    int part = t & 3;
    if (rbase + erow < n) {
        float y[16];
#pragma unroll
        for (int k = 0; k < 16; k++) y[k] = sY[erow * 17 + k];

        float o[10];
#pragma unroll
        for (int c = 0; c < 10; c++) o[c] = sB[part * 10 + c];
#pragma unroll
        for (int k = 0; k < H1Q; k++) {
            float h = y[k];
#pragma unroll
            for (int c = 0; c < 10; c++)
                o[c] = fmaf(h, sW[k * CQ + part * 10 + c], o[c]);
        }
        float m = 0.f;                      // relu floor
#pragma unroll
        for (int c = 0; c < 10; c++) {
            o[c] = fmaxf(o[c], 0.f);
            m = fmaxf(m, o[c]);
        }
        m = fmaxf(m, __shfl_xor_sync(0xffffffffu, m, 1));
        m = fmaxf(m, __shfl_xor_sync(0xffffffffu, m, 2));
        float s = 0.f;
#pragma unroll
        for (int c = 0; c < 10; c++) s += __expf(o[c] - m);
        s += __shfl_xor_sync(0xffffffffu, s, 1);
        s += __shfl_xor_sync(0xffffffffu, s, 2);
        float l = __logf(s) + m;

        float2* op = reinterpret_cast<float2*>(
            out + (size_t)(rbase + erow) * CQ + part * 10);
#pragma unroll
        for (int q = 0; q < 5; q++)
            op[q] = make_float2(o[2 * q] - l, o[2 * q + 1] - l);
    }
}

// ---------------------------------------------------------------------------
// Inputs (metadata order): H, A_vals, W1, b1, W2, b2, A_rows, A_cols
// ---------------------------------------------------------------------------
extern "C" void kernel_launch(void* const* d_in, const int* in_sizes, int n_in,
                              void* d_out, int out_size) {
    const float* Hm     = (const float*)d_in[0];
    const float* A_vals = (const float*)d_in[1];
    const float* W1     = (const float*)d_in[2];
    const float* b1     = (const float*)d_in[3];
    const float* W2     = (const float*)d_in[4];
    const float* b2     = (const float*)d_in[5];
    const int*   A_rows = (const int*)d_in[6];
    const int*   A_cols = (const int*)d_in[7];

    int n   = in_sizes[0] / DQ;
    int nnz = in_sizes[1];
    float* out = (float*)d_out;

    void* cnt_ptr = nullptr;
    cudaGetSymbolAddress(&cnt_ptr, g_cnt);
    cudaMemsetAsync(cnt_ptr, 0, (size_t)(N_MAX + 1) * sizeof(int), 0);

    int gemm_blocks    = (n + 511) / 512;
    int scatter_blocks = (nnz / 8 + 256) / 256;
    gemm_scatter_kernel<<<gemm_blocks + scatter_blocks, 256>>>(
        Hm, W1, A_rows, A_cols, A_vals, n, nnz, gemm_blocks);

    spmm1_kernel<<<(n + 63) / 64, 256>>>(b1, n);
    spmm2_epi_kernel<<<(n + 63) / 64, 256>>>(W2, b2, out, n);
}